// round 11
// baseline (speedup 1.0000x reference)
#include <cuda_runtime.h>
#include <cuda_bf16.h>
#include <math_constants.h>
#include <cstdint>

#define NN 30000
#define EE 300000
#define GG 128
#define IN_DIM 128
#define HID 64
#define HEADS 4
#define CH 256            // HEADS*HID
#define NC 10
#define EPS 1e-5f
#define SLOPE 0.2f

typedef unsigned long long u64;

// ---------------- scratch (device globals; no allocation allowed) ----------
__device__ float g_xl[NN * CH];
__device__ float g_xr[NN * CH];
__device__ float g_h[NN * CH];
__device__ float g_agg[NN * CH];
__device__ __align__(16) __nv_bfloat16 g_ah[NN * CH];
__device__ __align__(16) __nv_bfloat16 g_al[NN * CH];
__device__ __align__(16) __nv_bfloat16 g_wthi[2 * CH * CH];  // [z][n][k] stride K
__device__ __align__(16) __nv_bfloat16 g_wtlo[2 * CH * CH];
__device__ int   g_deg[NN];
__device__ int   g_off[NN + 1];
__device__ int   g_cur[NN];
__device__ int   g_csr[EE];
__device__ double g_bnsum[CH];
__device__ double g_bnsq[CH];
__device__ float g_pool[GG * HID];
__device__ float g_cnt[GG];

// ---------------- mma helper (fragment layout per PTX ISA manual) -----------
__device__ __forceinline__ void mma_bf16(float* d, const uint32_t* a, const uint32_t* b) {
    asm volatile("mma.sync.aligned.m16n8k16.row.col.f32.bf16.bf16.f32 "
                 "{%0,%1,%2,%3}, {%4,%5,%6,%7}, {%8,%9}, {%0,%1,%2,%3};"
                 : "+f"(d[0]), "+f"(d[1]), "+f"(d[2]), "+f"(d[3])
                 : "r"(a[0]), "r"(a[1]), "r"(a[2]), "r"(a[3]),
                   "r"(b[0]), "r"(b[1]));
}
__device__ __forceinline__ uint32_t ld32(const void* p) {
    return *(const uint32_t*)p;
}

// ---------------- CSR build -------------------------------------------------
__global__ void deg_clear_kernel() {
    int tid = blockIdx.x * blockDim.x + threadIdx.x;
    if (tid < NN) g_deg[tid] = 0;
}
__global__ void deg_count_kernel(const int* __restrict__ ei) {
    int e = blockIdx.x * blockDim.x + threadIdx.x;
    if (e < EE) atomicAdd(&g_deg[ei[EE + e]], 1);
}
__global__ void scan_kernel() {
    __shared__ int warp_sums[32];
    int t = threadIdx.x;
    int lane = t & 31, wid = t >> 5;
    int carry = 0;
    if (t == 0) g_off[0] = 0;
    for (int base = 0; base < NN; base += 1024) {
        int i = base + t;
        int v = (i < NN) ? g_deg[i] : 0;
        int x = v;
#pragma unroll
        for (int off = 1; off < 32; off <<= 1) {
            int y = __shfl_up_sync(0xffffffffu, x, off);
            if (lane >= off) x += y;
        }
        if (lane == 31) warp_sums[wid] = x;
        __syncthreads();
        if (wid == 0) {
            int w = warp_sums[lane];
#pragma unroll
            for (int off = 1; off < 32; off <<= 1) {
                int y = __shfl_up_sync(0xffffffffu, w, off);
                if (lane >= off) w += y;
            }
            warp_sums[lane] = w;
        }
        __syncthreads();
        int incl = x + (wid ? warp_sums[wid - 1] : 0) + carry;
        if (i < NN) { g_off[i + 1] = incl; g_cur[i] = incl - v; }
        carry += warp_sums[31];
        __syncthreads();
    }
}
__global__ void scatter_kernel(const int* __restrict__ ei) {
    int e = blockIdx.x * blockDim.x + threadIdx.x;
    if (e < EE) {
        int s = ei[e], d = ei[EE + e];
        int p = atomicAdd(&g_cur[d], 1);
        g_csr[p] = s;
    }
}

// ---------------- A split: fp32 -> bf16 hi/lo -------------------------------
// a_sel selects the source INSIDE device code (host must never take the
// address of a __device__ symbol — that was the R6-R9 all-zeros bug).
__global__ void asplit_kernel(const float* __restrict__ xin, int a_sel, int total) {
    const float* src = a_sel ? g_h : xin;
    int i = (blockIdx.x * blockDim.x + threadIdx.x) * 4;
    if (i >= total) return;
    float4 v = *(const float4*)(src + i);
    __nv_bfloat162 h01 = __floats2bfloat162_rn(v.x, v.y);
    __nv_bfloat162 h23 = __floats2bfloat162_rn(v.z, v.w);
    float2 f01 = __bfloat1622float2(h01);
    float2 f23 = __bfloat1622float2(h23);
    __nv_bfloat162 l01 = __floats2bfloat162_rn(v.x - f01.x, v.y - f01.y);
    __nv_bfloat162 l23 = __floats2bfloat162_rn(v.z - f23.x, v.w - f23.y);
    *(__nv_bfloat162*)(g_ah + i)     = h01;
    *(__nv_bfloat162*)(g_ah + i + 2) = h23;
    *(__nv_bfloat162*)(g_al + i)     = l01;
    *(__nv_bfloat162*)(g_al + i + 2) = l23;
}

// ---------------- W transpose + split: [K,256] fp32 -> [256,K] bf16 hi/lo ---
__global__ void wsplit_kernel(const float* __restrict__ W0,
                              const float* __restrict__ W1, int K) {
    __shared__ float tile[32][33];
    const float* W = blockIdx.z ? W1 : W0;
    __nv_bfloat16* whi = g_wthi + blockIdx.z * CH * CH;
    __nv_bfloat16* wlo = g_wtlo + blockIdx.z * CH * CH;
    int k0 = blockIdx.x * 32, n0 = blockIdx.y * 32;
    for (int r = threadIdx.y; r < 32; r += 8)
        tile[r][threadIdx.x] = W[(k0 + r) * CH + n0 + threadIdx.x];
    __syncthreads();
    for (int r = threadIdx.y; r < 32; r += 8) {
        float v = tile[threadIdx.x][r];        // W[k0+tx][n0+r]
        __nv_bfloat16 h = __float2bfloat16_rn(v);
        __nv_bfloat16 l = __float2bfloat16_rn(v - __bfloat162float(h));
        whi[(n0 + r) * K + k0 + threadIdx.x] = h;
        wlo[(n0 + r) * K + k0 + threadIdx.x] = l;
    }
}

// ---------------- mma.sync GEMM, fragments direct from global ---------------
// Warp tile 32m x 32n (2x4 m16n8k16), block 8 warps = 64m x 128n.
__global__ void gemm_mma_kernel(int K) {
    int lane = threadIdx.x & 31, wid = threadIdx.x >> 5;
    int z = blockIdx.z;
    const char* Ahb = (const char*)g_ah;
    const char* Alb = (const char*)g_al;
    const char* Bhb = (const char*)(g_wthi + z * CH * CH);
    const char* Blb = (const char*)(g_wtlo + z * CH * CH);
    float* C = z ? g_xr : g_xl;

    int m0 = blockIdx.x * 64 + (wid & 1) * 32;
    int n0 = blockIdx.y * 128 + (wid >> 1) * 32;
    int g = lane >> 2;                 // group row within 8
    int koff = (lane & 3) * 2;         // k element offset within 8

    size_t aoff[2][2];
#pragma unroll
    for (int mt = 0; mt < 2; mt++) {
        int r0 = m0 + mt * 16 + g;
        int r1 = r0 + 8;
        if (r0 >= NN) r0 = NN - 1;
        if (r1 >= NN) r1 = NN - 1;
        aoff[mt][0] = (size_t)r0 * K * 2;
        aoff[mt][1] = (size_t)r1 * K * 2;
    }
    size_t boff[4];
#pragma unroll
    for (int nt = 0; nt < 4; nt++)
        boff[nt] = (size_t)(n0 + nt * 8 + g) * K * 2;

    float acc[2][4][4];
#pragma unroll
    for (int i = 0; i < 2; i++)
#pragma unroll
        for (int j = 0; j < 4; j++)
#pragma unroll
            for (int q = 0; q < 4; q++) acc[i][j][q] = 0.f;

    for (int k0 = 0; k0 < K; k0 += 16) {
        size_t kb2 = (size_t)(k0 + koff) * 2;
        uint32_t ah[2][4], al[2][4], bh[4][2], bl[4][2];
#pragma unroll
        for (int mt = 0; mt < 2; mt++) {
            ah[mt][0] = ld32(Ahb + aoff[mt][0] + kb2);
            ah[mt][1] = ld32(Ahb + aoff[mt][1] + kb2);
            ah[mt][2] = ld32(Ahb + aoff[mt][0] + kb2 + 16);
            ah[mt][3] = ld32(Ahb + aoff[mt][1] + kb2 + 16);
            al[mt][0] = ld32(Alb + aoff[mt][0] + kb2);
            al[mt][1] = ld32(Alb + aoff[mt][1] + kb2);
            al[mt][2] = ld32(Alb + aoff[mt][0] + kb2 + 16);
            al[mt][3] = ld32(Alb + aoff[mt][1] + kb2 + 16);
        }
#pragma unroll
        for (int nt = 0; nt < 4; nt++) {
            bh[nt][0] = ld32(Bhb + boff[nt] + kb2);
            bh[nt][1] = ld32(Bhb + boff[nt] + kb2 + 16);
            bl[nt][0] = ld32(Blb + boff[nt] + kb2);
            bl[nt][1] = ld32(Blb + boff[nt] + kb2 + 16);
        }
#pragma unroll
        for (int mt = 0; mt < 2; mt++)
#pragma unroll
            for (int nt = 0; nt < 4; nt++) {
                mma_bf16(acc[mt][nt], ah[mt], bh[nt]);
                mma_bf16(acc[mt][nt], al[mt], bh[nt]);
                mma_bf16(acc[mt][nt], ah[mt], bl[nt]);
            }
    }
#pragma unroll
    for (int mt = 0; mt < 2; mt++)
#pragma unroll
        for (int nt = 0; nt < 4; nt++) {
            int r0 = m0 + mt * 16 + g;
            int c0 = n0 + nt * 8 + koff;
            if (r0 < NN)
                *(float2*)(C + (size_t)r0 * CH + c0) =
                    make_float2(acc[mt][nt][0], acc[mt][nt][1]);
            if (r0 + 8 < NN)
                *(float2*)(C + (size_t)(r0 + 8) * CH + c0) =
                    make_float2(acc[mt][nt][2], acc[mt][nt][3]);
        }
}

// ---------------- fused GATv2 aggregation: warp per dst node ----------------
__global__ void gat_kernel(const float* __restrict__ att) {
    int node = blockIdx.x * 8 + (threadIdx.x >> 5);
    if (node >= NN) return;
    int lane = threadIdx.x & 31;
    int cbase = lane * 8;

    float4 at0 = *(const float4*)(att + cbase);
    float4 at1 = *(const float4*)(att + cbase + 4);
    const float4* xrp = (const float4*)(g_xr + node * CH + cbase);
    float4 xr0 = xrp[0], xr1 = xrp[1];

    float m = -CUDART_INF_F, s = 0.f;
    float acc[8];
#pragma unroll
    for (int j = 0; j < 8; j++) acc[j] = 0.f;

    int start = g_off[node], end = g_off[node + 1];
    for (int idx = start - 1; idx < end; idx++) {
        int src = (idx < start) ? node : g_csr[idx];
        const float4* xlp = (const float4*)(g_xl + src * CH + cbase);
        float4 xl0 = xlp[0], xl1 = xlp[1];

        float e;
        {
            float q, t = 0.f;
            q = xl0.x + xr0.x; q = q > 0.f ? q : SLOPE * q; t += q * at0.x;
            q = xl0.y + xr0.y; q = q > 0.f ? q : SLOPE * q; t += q * at0.y;
            q = xl0.z + xr0.z; q = q > 0.f ? q : SLOPE * q; t += q * at0.z;
            q = xl0.w + xr0.w; q = q > 0.f ? q : SLOPE * q; t += q * at0.w;
            q = xl1.x + xr1.x; q = q > 0.f ? q : SLOPE * q; t += q * at1.x;
            q = xl1.y + xr1.y; q = q > 0.f ? q : SLOPE * q; t += q * at1.y;
            q = xl1.z + xr1.z; q = q > 0.f ? q : SLOPE * q; t += q * at1.z;
            q = xl1.w + xr1.w; q = q > 0.f ? q : SLOPE * q; t += q * at1.w;
            e = t;
        }
        e += __shfl_xor_sync(0xffffffffu, e, 1);
        e += __shfl_xor_sync(0xffffffffu, e, 2);
        e += __shfl_xor_sync(0xffffffffu, e, 4);

        float mnew = fmaxf(m, e);
        float c = __expf(m - mnew);
        float p = __expf(e - mnew);
        s = s * c + p;
        acc[0] = acc[0] * c + p * xl0.x;
        acc[1] = acc[1] * c + p * xl0.y;
        acc[2] = acc[2] * c + p * xl0.z;
        acc[3] = acc[3] * c + p * xl0.w;
        acc[4] = acc[4] * c + p * xl1.x;
        acc[5] = acc[5] * c + p * xl1.y;
        acc[6] = acc[6] * c + p * xl1.z;
        acc[7] = acc[7] * c + p * xl1.w;
        m = mnew;
    }
    float inv = 1.f / s;
    float4* op = (float4*)(g_agg + node * CH + cbase);
    op[0] = make_float4(acc[0] * inv, acc[1] * inv, acc[2] * inv, acc[3] * inv);
    op[1] = make_float4(acc[4] * inv, acc[5] * inv, acc[6] * inv, acc[7] * inv);
}

// ---------------- head mean (last layer, concat=False) ----------------------
__global__ void headmean_kernel() {
    int tid = blockIdx.x * blockDim.x + threadIdx.x;
    if (tid >= NN * HID) return;
    int n = tid >> 6;
    int c = tid & 63;
    const float* a = g_agg + n * CH;
    g_xr[tid] = 0.25f * (a[c] + a[HID + c] + a[2 * HID + c] + a[3 * HID + c]);
}

// ---------------- batch norm (train stats) + ELU ----------------------------
__global__ void clear_bn_kernel() {
    int t = threadIdx.x;
    if (t < CH) { g_bnsum[t] = 0.0; g_bnsq[t] = 0.0; }
}
__global__ void bn_stats_kernel(int sel) {
    int C = sel ? HID : CH;
    const float* X = sel ? g_xr : g_agg;
    int ch = threadIdx.x;
    float s = 0.f, q = 0.f;
    for (int r = blockIdx.x; r < NN; r += gridDim.x) {
        float v = X[r * C + ch];
        s += v;
        q += v * v;
    }
    atomicAdd(&g_bnsum[ch], (double)s);
    atomicAdd(&g_bnsq[ch], (double)q);
}
__global__ void bn_apply_kernel(const float* __restrict__ gam,
                                const float* __restrict__ bet, int sel) {
    int C = sel ? HID : CH;
    const float* X = sel ? g_xr : g_agg;
    int tid = blockIdx.x * blockDim.x + threadIdx.x;
    if (tid >= NN * C) return;
    int ch = tid & (C - 1);
    float mu = (float)(g_bnsum[ch] * (1.0 / NN));
    float var = (float)(g_bnsq[ch] * (1.0 / NN)) - mu * mu;
    float y = gam[ch] * (X[tid] - mu) * rsqrtf(var + EPS) + bet[ch];
    g_h[tid] = y > 0.f ? y : expm1f(y);        // ELU
}

// ---------------- pooling + MLP head ----------------------------------------
__global__ void clear_pool_kernel() {
    int tid = blockIdx.x * blockDim.x + threadIdx.x;
    if (tid < GG * HID) g_pool[tid] = 0.f;
    if (tid < GG) g_cnt[tid] = 0.f;
}
__global__ void pool_sum_kernel(const int* __restrict__ batch) {
    int tid = blockIdx.x * blockDim.x + threadIdx.x;
    if (tid >= NN * HID) return;
    int n = tid >> 6;
    int c = tid & 63;
    atomicAdd(&g_pool[batch[n] * HID + c], g_h[tid]);
}
__global__ void pool_cnt_kernel(const int* __restrict__ batch) {
    int tid = blockIdx.x * blockDim.x + threadIdx.x;
    if (tid >= NN) return;
    atomicAdd(&g_cnt[batch[tid]], 1.f);
}
__global__ void head_kernel(const float* __restrict__ fc1w,
                            const float* __restrict__ fc1b,
                            const float* __restrict__ fc2w,
                            const float* __restrict__ fc2b,
                            float* __restrict__ out) {
    __shared__ float p[HID], h1[HID];
    int g = blockIdx.x, t = threadIdx.x;
    float cnt = fmaxf(g_cnt[g], 1.f);
    p[t] = g_pool[g * HID + t] / cnt;
    __syncthreads();
    float a = fc1b[t];
#pragma unroll
    for (int k = 0; k < HID; k++) a += p[k] * fc1w[k * HID + t];
    h1[t] = fmaxf(a, 0.f);
    __syncthreads();
    if (t < NC) {
        float o = fc2b[t];
#pragma unroll
        for (int k = 0; k < HID; k++) o += h1[k] * fc2w[k * NC + t];
        out[g * NC + t] = o;
    }
}

// ---------------- launcher ---------------------------------------------------
static inline int cdiv(int a, int b) { return (a + b - 1) / b; }

extern "C" void kernel_launch(void* const* d_in, const int* in_sizes, int n_in,
                              void* d_out, int out_size) {
    const float* x = (const float*)d_in[0];
    const int* ei = (const int*)d_in[1];
    const int* batch = (const int*)d_in[2];
    const float *Wl[4], *Wr[4], *att[4], *gam[4], *bet[4];
    for (int i = 0; i < 4; i++) {
        Wl[i] = (const float*)d_in[3 + 6 * i];
        Wr[i] = (const float*)d_in[4 + 6 * i];
        att[i] = (const float*)d_in[5 + 6 * i];
        gam[i] = (const float*)d_in[7 + 6 * i];
        bet[i] = (const float*)d_in[8 + 6 * i];
    }
    const float* fc1w = (const float*)d_in[27];
    const float* fc1b = (const float*)d_in[28];
    const float* fc2w = (const float*)d_in[29];
    const float* fc2b = (const float*)d_in[30];
    float* out = (float*)d_out;

    // ---- build CSR once per call
    deg_clear_kernel<<<cdiv(NN, 256), 256>>>();
    deg_count_kernel<<<cdiv(EE, 256), 256>>>(ei);
    scan_kernel<<<1, 1024>>>();
    scatter_kernel<<<cdiv(EE, 256), 256>>>(ei);

    for (int i = 0; i < 4; i++) {
        int K = (i == 0) ? IN_DIM : CH;
        int a_sel = (i == 0) ? 0 : 1;

        asplit_kernel<<<cdiv(NN * K / 4, 256), 256>>>(x, a_sel, NN * K);
        dim3 wgrid(K / 32, CH / 32, 2);
        wsplit_kernel<<<wgrid, dim3(32, 8)>>>(Wl[i], Wr[i], K);
        dim3 ggrid(cdiv(NN, 64), CH / 128, 2);
        gemm_mma_kernel<<<ggrid, 256>>>(K);

        gat_kernel<<<cdiv(NN, 8), 256>>>(att[i]);

        if (i < 3) {
            clear_bn_kernel<<<1, 256>>>();
            bn_stats_kernel<<<256, CH>>>(0);
            bn_apply_kernel<<<cdiv(NN * CH, 256), 256>>>(gam[i], bet[i], 0);
        } else {
            headmean_kernel<<<cdiv(NN * HID, 256), 256>>>();
            clear_bn_kernel<<<1, 256>>>();
            bn_stats_kernel<<<256, HID>>>(1);
            bn_apply_kernel<<<cdiv(NN * HID, 256), 256>>>(gam[i], bet[i], 1);
        }
    }

    clear_pool_kernel<<<cdiv(GG * HID, 256), 256>>>();
    pool_sum_kernel<<<cdiv(NN * HID, 256), 256>>>(batch);
    pool_cnt_kernel<<<cdiv(NN, 256), 256>>>(batch);
    head_kernel<<<GG, HID>>>(fc1w, fc1b, fc2w, fc2b, out);
}